// round 2
// baseline (speedup 1.0000x reference)
#include <cuda_runtime.h>
#include <cstdint>

#define SEQ   2048
#define BATCH 64
#define KIN   256
#define HID   256
#define G4H   1024   // 4*HID

// Scratch: precomputed x @ Wi^T + (bi+bh), layout [t][b][g*256+j]
__device__ float g_preact[(size_t)SEQ * BATCH * G4H];   // 512 MB
// h ping-pong exchange buffer: h for step t (t>=1) lives in g_hbuf[t&1]
__device__ float g_hbuf[2][BATCH * HID];
// monotonic barrier counter (reset by init kernel each launch)
__device__ unsigned int g_bar;

__global__ void init_bar_kernel() { g_bar = 0u; }

// ---------------------------------------------------------------------------
// Kernel 1: preact_x[m][n] = sum_k x[m][k]*Wi[n][k] + bi[n] + bh[n]
//           M = SEQ*BATCH = 131072, N = 1024, K = 256
// Block tile 128(m) x 64(n), 256 threads, thread tile 8x4, K-chunks of 16.
// ---------------------------------------------------------------------------
__global__ void __launch_bounds__(256) gemm_x_kernel(
    const float* __restrict__ x, const float* __restrict__ Wi,
    const float* __restrict__ bi, const float* __restrict__ bh)
{
    __shared__ float As[16][129];
    __shared__ float Bs[16][65];

    const int m0 = blockIdx.y * 128;
    const int n0 = blockIdx.x * 64;
    const int u  = threadIdx.x;

    const int tm = u >> 4;     // 0..15
    const int tn = u & 15;     // 0..15

    float acc[8][4];
#pragma unroll
    for (int i = 0; i < 8; i++)
#pragma unroll
        for (int j = 0; j < 4; j++) acc[i][j] = 0.f;

    for (int kc = 0; kc < KIN; kc += 16) {
        // load A tile: 128 rows x 16 k  (512 float4, 2 per thread)
#pragma unroll
        for (int q = 0; q < 2; q++) {
            int f  = u * 2 + q;          // 0..511
            int m  = f >> 2;             // 0..127
            int kq = f & 3;              // 0..3
            float4 v = *(const float4*)&x[(size_t)(m0 + m) * KIN + kc + kq * 4];
            As[kq * 4 + 0][m] = v.x;
            As[kq * 4 + 1][m] = v.y;
            As[kq * 4 + 2][m] = v.z;
            As[kq * 4 + 3][m] = v.w;
        }
        {   // load B tile: 64 rows x 16 k (256 float4, 1 per thread)
            int n  = u >> 2;             // 0..63
            int kq = u & 3;
            float4 v = *(const float4*)&Wi[(size_t)(n0 + n) * KIN + kc + kq * 4];
            Bs[kq * 4 + 0][n] = v.x;
            Bs[kq * 4 + 1][n] = v.y;
            Bs[kq * 4 + 2][n] = v.z;
            Bs[kq * 4 + 3][n] = v.w;
        }
        __syncthreads();

#pragma unroll
        for (int kk = 0; kk < 16; kk++) {
            float a[8], b[4];
#pragma unroll
            for (int i = 0; i < 8; i++) a[i] = As[kk][tm * 8 + i];
#pragma unroll
            for (int j = 0; j < 4; j++) b[j] = Bs[kk][tn * 4 + j];
#pragma unroll
            for (int i = 0; i < 8; i++)
#pragma unroll
                for (int j = 0; j < 4; j++) acc[i][j] = fmaf(a[i], b[j], acc[i][j]);
        }
        __syncthreads();
    }

    // bias per output column
    float bias[4];
#pragma unroll
    for (int j = 0; j < 4; j++) {
        int n = n0 + tn * 4 + j;
        bias[j] = bi[n] + bh[n];
    }

#pragma unroll
    for (int i = 0; i < 8; i++) {
        int m = m0 + tm * 8 + i;
        float4 v;
        v.x = acc[i][0] + bias[0];
        v.y = acc[i][1] + bias[1];
        v.z = acc[i][2] + bias[2];
        v.w = acc[i][3] + bias[3];
        *(float4*)&g_preact[(size_t)m * G4H + n0 + tn * 4] = v;
    }
}

// ---------------------------------------------------------------------------
// Kernel 2: persistent recurrent kernel.
// 128 blocks = 16 j-slices (16 hidden units each) x 8 batch-slices (8 each).
// Wh slice (4 gates x 16 j x 256 k = 64KB) kept in registers: 64 floats/thread.
// Per step: load h tile -> register-weight GEMM (h broadcast from smem)
//           -> smem K-reduction -> gates (threads 0..127 own one (b,j) each)
//           -> write h to ys + ping-pong buffer -> global spin barrier.
// ---------------------------------------------------------------------------
__device__ __forceinline__ float sigf(float x) {
    return __fdividef(1.f, 1.f + __expf(-x));
}
__device__ __forceinline__ float tanhf_(float x) {
    return 2.f * sigf(2.f * x) - 1.f;
}

__global__ void __launch_bounds__(256, 1) lstm_rec_kernel(
    const float* __restrict__ h0, const float* __restrict__ c0,
    const float* __restrict__ Wh, float* __restrict__ out)
{
    __shared__ float hs[8][256];        // h tile: 8 batches x 256
    __shared__ float reds[64 * 33];     // K-partial reduction, padded stride 33

    const int u   = threadIdx.x;
    const int jb  = blockIdx.x & 15;    // j-slice index   (16)
    const int bb  = blockIdx.x >> 4;    // batch-slice idx (8)
    const int j0  = jb * 16;
    const int b0  = bb * 8;

    const int wid = u >> 5;             // warp 0..7
    const int l   = u & 31;
    const int ch  = wid >> 2;           // combo half 0/1
    const int kq  = wid & 3;            // k quarter  0..3  (64 k each)
    const int cmb = ch * 32 + l;        // 0..63
    const int g   = cmb >> 4;           // gate 0..3 (i,f,o,g)
    const int jj  = cmb & 15;           // local j

    // load this thread's 64 weights into registers
    float w[64];
    {
        const float* wrow = Wh + (size_t)(g * HID + j0 + jj) * HID + kq * 64;
#pragma unroll
        for (int q = 0; q < 16; q++) {
            float4 v = *(const float4*)&wrow[q * 4];
            w[q * 4 + 0] = v.x; w[q * 4 + 1] = v.y;
            w[q * 4 + 2] = v.z; w[q * 4 + 3] = v.w;
        }
    }

    // gate/state ownership for threads 0..127: one (batch, hidden) pair each
    const int tb = u >> 4;   // 0..7 (valid when u<128)
    const int tj = u & 15;   // 0..15
    float cst = 0.f, hlast = 0.f;
    if (u < 128) cst = c0[(b0 + tb) * HID + j0 + tj];

    for (int t = 0; t < SEQ; t++) {
        // prefetch input-projection preacts for this step (independent of h)
        float px0 = 0.f, px1 = 0.f, px2 = 0.f, px3 = 0.f;
        if (u < 128) {
            const float* pp = g_preact + ((size_t)t * BATCH + b0 + tb) * G4H + j0 + tj;
            px0 = pp[0 * HID];
            px1 = pp[1 * HID];
            px2 = pp[2 * HID];
            px3 = pp[3 * HID];
        }

        // load h_t tile into smem (bypass L1: written by other SMs)
        {
            const float* hsrc = (t == 0) ? h0 : g_hbuf[t & 1];
#pragma unroll
            for (int q = 0; q < 2; q++) {
                int f  = u * 2 + q;      // 0..511
                int b  = f >> 6;         // 0..7
                int ko = (f & 63) * 4;   // 0..252
                float4 v = __ldcv((const float4*)&hsrc[(size_t)(b0 + b) * HID + ko]);
                *(float4*)&hs[b][ko] = v;
            }
        }
        __syncthreads();

        // register-weight GEMM: acc[b] = sum over this thread's k-quarter
        float acc[8];
#pragma unroll
        for (int b = 0; b < 8; b++) acc[b] = 0.f;
#pragma unroll
        for (int k4 = 0; k4 < 16; k4++) {
#pragma unroll
            for (int b = 0; b < 8; b++) {
                float4 hv = *(const float4*)&hs[b][kq * 64 + k4 * 4];  // broadcast
                acc[b] = fmaf(hv.x, w[k4 * 4 + 0], acc[b]);
                acc[b] = fmaf(hv.y, w[k4 * 4 + 1], acc[b]);
                acc[b] = fmaf(hv.z, w[k4 * 4 + 2], acc[b]);
                acc[b] = fmaf(hv.w, w[k4 * 4 + 3], acc[b]);
            }
        }
#pragma unroll
        for (int b = 0; b < 8; b++)
            reds[cmb * 33 + kq * 8 + b] = acc[b];
        __syncthreads();

        if (u < 128) {
            float p[4];
#pragma unroll
            for (int gg = 0; gg < 4; gg++) {
                int cc = gg * 16 + tj;
                p[gg] = reds[cc * 33 + 0 + tb] + reds[cc * 33 + 8 + tb]
                      + reds[cc * 33 + 16 + tb] + reds[cc * 33 + 24 + tb];
            }
            p[0] += px0; p[1] += px1; p[2] += px2; p[3] += px3;

            float it = sigf(p[0]);
            float ft = sigf(p[1]);
            float ot = sigf(p[2]);
            float gt = tanhf_(p[3]);
            cst = cst * ft + it * gt;
            float ht = ot * tanhf_(cst);
            hlast = ht;

            out[((size_t)t * BATCH + b0 + tb) * HID + j0 + tj] = ht;
            g_hbuf[(t + 1) & 1][(b0 + tb) * HID + j0 + tj] = ht;
            __threadfence();   // release h writes before arriving
        }
        __syncthreads();

        if (t < SEQ - 1) {
            if (u == 0) {
                atomicAdd(&g_bar, 1u);
                const unsigned target = (unsigned)(t + 1) * 128u;
                while (*((volatile unsigned*)&g_bar) < target) { }
                __threadfence();   // acquire (also invalidates L1D)
            }
            __syncthreads();
        }
    }

    // final states: h_n then c_n after ys
    if (u < 128) {
        const size_t base = (size_t)SEQ * BATCH * HID;
        const int idx = (b0 + tb) * HID + j0 + tj;
        out[base + idx]               = hlast;
        out[base + BATCH * HID + idx] = cst;
    }
}

// ---------------------------------------------------------------------------
extern "C" void kernel_launch(void* const* d_in, const int* in_sizes, int n_in,
                              void* d_out, int out_size)
{
    const float* x  = (const float*)d_in[0];
    const float* h0 = (const float*)d_in[1];
    const float* c0 = (const float*)d_in[2];
    const float* Wi = (const float*)d_in[3];
    const float* bi = (const float*)d_in[4];
    const float* Wh = (const float*)d_in[5];
    const float* bh = (const float*)d_in[6];
    float* out = (float*)d_out;

    init_bar_kernel<<<1, 1>>>();

    dim3 grid1(G4H / 64, (SEQ * BATCH) / 128);   // 16 x 1024
    gemm_x_kernel<<<grid1, 256>>>(x, Wi, bi, bh);

    lstm_rec_kernel<<<128, 256>>>(h0, c0, Wh, out);
}

// round 4
// speedup vs baseline: 1.3319x; 1.3319x over previous
#include <cuda_runtime.h>
#include <cuda_bf16.h>
#include <cstdint>

typedef unsigned long long ull;

#define SEQ   2048
#define BATCH 64
#define KIN   256
#define HID   256
#define G4H   1024   // 4*HID
#define MTOT  (SEQ * BATCH)   // 131072

// ---------------- scratch (device globals; no allocation allowed) ----------
__device__ float g_preact[(size_t)SEQ * BATCH * G4H];          // 512 MB
__device__ __nv_bfloat16 g_xh[(size_t)MTOT * KIN];             // 64 MB
__device__ __nv_bfloat16 g_xl[(size_t)MTOT * KIN];             // 64 MB
__device__ __nv_bfloat16 g_wih[(size_t)G4H * KIN];
__device__ __nv_bfloat16 g_wil[(size_t)G4H * KIN];
__device__ float g_bias[G4H];
__device__ float g_hbuf[2][BATCH * HID];
__device__ unsigned int g_barG[256];    // 8 group counters, 128B apart

// ---------------- small helpers -------------------------------------------
__device__ __forceinline__ uint32_t smem_u32(const void* p) {
    uint32_t a;
    asm("{ .reg .u64 t; cvta.to.shared.u64 t, %1; cvt.u32.u64 %0, t; }"
        : "=r"(a) : "l"(p));
    return a;
}
__device__ __forceinline__ ull ffma2(ull a, ull b, ull c) {
    ull d;
    asm("fma.rn.f32x2 %0, %1, %2, %3;" : "=l"(d) : "l"(a), "l"(b), "l"(c));
    return d;
}
__device__ __forceinline__ ull pk2(float x, float y) {
    ull r;
    asm("mov.b64 %0, {%1, %2};" : "=l"(r)
        : "r"(__float_as_uint(x)), "r"(__float_as_uint(y)));
    return r;
}
__device__ __forceinline__ void upk2(ull v, float& x, float& y) {
    uint32_t a, b;
    asm("mov.b64 {%0, %1}, %2;" : "=r"(a), "=r"(b) : "l"(v));
    x = __uint_as_float(a); y = __uint_as_float(b);
}
__device__ __forceinline__ float sigf(float x) {
    return __fdividef(1.f, 1.f + __expf(-x));
}
__device__ __forceinline__ float tanhf_(float x) { return 2.f * sigf(2.f * x) - 1.f; }

__device__ __forceinline__ void ldm_x4(uint32_t* r, uint32_t addr) {
    asm volatile("ldmatrix.sync.aligned.m8n8.x4.shared.b16 {%0,%1,%2,%3}, [%4];"
                 : "=r"(r[0]), "=r"(r[1]), "=r"(r[2]), "=r"(r[3]) : "r"(addr));
}
__device__ __forceinline__ void ldm_x2(uint32_t* r, uint32_t addr) {
    asm volatile("ldmatrix.sync.aligned.m8n8.x2.shared.b16 {%0,%1}, [%2];"
                 : "=r"(r[0]), "=r"(r[1]) : "r"(addr));
}
__device__ __forceinline__ void mma16816(float* d, const uint32_t* a,
                                         const uint32_t* b) {
    asm volatile(
        "mma.sync.aligned.m16n8k16.row.col.f32.bf16.bf16.f32 "
        "{%0,%1,%2,%3}, {%4,%5,%6,%7}, {%8,%9}, {%0,%1,%2,%3};"
        : "+f"(d[0]), "+f"(d[1]), "+f"(d[2]), "+f"(d[3])
        : "r"(a[0]), "r"(a[1]), "r"(a[2]), "r"(a[3]), "r"(b[0]), "r"(b[1]));
}

// ---------------------------------------------------------------------------
// Kernel 0a: convert x -> bf16 hi/lo planes
// ---------------------------------------------------------------------------
__global__ void __launch_bounds__(256) convert_x_kernel(const float* __restrict__ x)
{
    const size_t n4 = (size_t)MTOT * KIN / 4;
    for (size_t i = (size_t)blockIdx.x * blockDim.x + threadIdx.x; i < n4;
         i += (size_t)gridDim.x * blockDim.x) {
        float4 v = ((const float4*)x)[i];
        __nv_bfloat16 h0 = __float2bfloat16(v.x);
        __nv_bfloat16 h1 = __float2bfloat16(v.y);
        __nv_bfloat16 h2 = __float2bfloat16(v.z);
        __nv_bfloat16 h3 = __float2bfloat16(v.w);
        __nv_bfloat16 l0 = __float2bfloat16(v.x - __bfloat162float(h0));
        __nv_bfloat16 l1 = __float2bfloat16(v.y - __bfloat162float(h1));
        __nv_bfloat16 l2 = __float2bfloat16(v.z - __bfloat162float(h2));
        __nv_bfloat16 l3 = __float2bfloat16(v.w - __bfloat162float(h3));
        __nv_bfloat162 ph0 = {h0, h1}, ph1 = {h2, h3};
        __nv_bfloat162 pl0 = {l0, l1}, pl1 = {l2, l3};
        uint2 uh = {*(uint32_t*)&ph0, *(uint32_t*)&ph1};
        uint2 ul = {*(uint32_t*)&pl0, *(uint32_t*)&pl1};
        ((uint2*)g_xh)[i] = uh;
        ((uint2*)g_xl)[i] = ul;
    }
}

// ---------------------------------------------------------------------------
// Kernel 0b: convert Wi -> bf16 hi/lo, combine bias, reset barriers
// ---------------------------------------------------------------------------
__global__ void __launch_bounds__(256) convert_w_kernel(
    const float* __restrict__ Wi, const float* __restrict__ bi,
    const float* __restrict__ bh)
{
    const size_t tid = (size_t)blockIdx.x * blockDim.x + threadIdx.x;
    const size_t n4 = (size_t)G4H * KIN / 4;   // 65536
    if (tid < n4) {
        float4 v = ((const float4*)Wi)[tid];
        __nv_bfloat16 h0 = __float2bfloat16(v.x);
        __nv_bfloat16 h1 = __float2bfloat16(v.y);
        __nv_bfloat16 h2 = __float2bfloat16(v.z);
        __nv_bfloat16 h3 = __float2bfloat16(v.w);
        __nv_bfloat16 l0 = __float2bfloat16(v.x - __bfloat162float(h0));
        __nv_bfloat16 l1 = __float2bfloat16(v.y - __bfloat162float(h1));
        __nv_bfloat16 l2 = __float2bfloat16(v.z - __bfloat162float(h2));
        __nv_bfloat16 l3 = __float2bfloat16(v.w - __bfloat162float(h3));
        __nv_bfloat162 ph0 = {h0, h1}, ph1 = {h2, h3};
        __nv_bfloat162 pl0 = {l0, l1}, pl1 = {l2, l3};
        uint2 uh = {*(uint32_t*)&ph0, *(uint32_t*)&ph1};
        uint2 ul = {*(uint32_t*)&pl0, *(uint32_t*)&pl1};
        ((uint2*)g_wih)[tid] = uh;
        ((uint2*)g_wil)[tid] = ul;
    }
    if (tid < G4H) g_bias[tid] = bi[tid] + bh[tid];
    if (tid < 256) g_barG[tid] = 0u;
}

// ---------------------------------------------------------------------------
// Kernel 1: bf16x3 GEMM via mma.sync.m16n8k16 (sm_103-safe, no tcgen05)
//   g_preact[m][n] = sum_k x[m][k]*Wi[n][k] + bias[n]
//   block 128(m)x128(n), 8 warps = 2m x 4n, warp tile 64x32.
//   K chunks of 32; per chunk 3 passes: Ah*Bh + Ah*Bl + Al*Bh.
// ---------------------------------------------------------------------------
#define LDP 40   // smem row stride in bf16 (80B: 16B-bank-conflict-free ldmatrix)

__global__ void __launch_bounds__(256) gemm_mma_kernel()
{
    __shared__ __nv_bfloat16 Ah[128][LDP], Al[128][LDP];
    __shared__ __nv_bfloat16 Bh[128][LDP], Bl[128][LDP];

    const int tid = threadIdx.x;
    const int w = tid >> 5, l = tid & 31;
    const int m0 = blockIdx.y * 128, n0 = blockIdx.x * 128;
    const int wm = w & 1;        // m half (64 rows)
    const int wn = w >> 1;       // n quarter (32 cols)

    float acc[4][4][4];
#pragma unroll
    for (int mi = 0; mi < 4; mi++)
#pragma unroll
        for (int ni = 0; ni < 4; ni++)
#pragma unroll
            for (int q = 0; q < 4; q++) acc[mi][ni][q] = 0.f;

    for (int kc = 0; kc < KIN; kc += 32) {
        // ---- fill 4 tiles: Ah, Al (rows m0..), Bh, Bl (rows n0..) ----
#pragma unroll
        for (int tb = 0; tb < 4; tb++) {
            const __nv_bfloat16* src =
                (tb == 0) ? g_xh : (tb == 1) ? g_xl : (tb == 2) ? g_wih : g_wil;
            const int row0 = (tb < 2) ? m0 : n0;
            __nv_bfloat16 (*dst)[LDP] =
                (tb == 0) ? Ah : (tb == 1) ? Al : (tb == 2) ? Bh : Bl;
#pragma unroll
            for (int i = tid; i < 512; i += 256) {
                int r = i >> 2, q = i & 3;
                uint4 v = *(const uint4*)(src + (size_t)(row0 + r) * KIN + kc + q * 8);
                *(uint2*)&dst[r][q * 8]     = make_uint2(v.x, v.y);
                *(uint2*)&dst[r][q * 8 + 4] = make_uint2(v.z, v.w);
            }
        }
        __syncthreads();

#pragma unroll
        for (int p = 0; p < 3; p++) {
            const __nv_bfloat16 (*Ap)[LDP] = (p == 2) ? Al : Ah;
            const __nv_bfloat16 (*Bp)[LDP] = (p == 1) ? Bl : Bh;
#pragma unroll
            for (int ks = 0; ks < 2; ks++) {
                uint32_t af[4][4], bf[4][2];
#pragma unroll
                for (int mi = 0; mi < 4; mi++)
                    ldm_x4(af[mi], smem_u32(
                        &Ap[wm * 64 + mi * 16 + (l & 15)][ks * 16 + (l >> 4) * 8]));
#pragma unroll
                for (int ni = 0; ni < 4; ni++)
                    ldm_x2(bf[ni], smem_u32(
                        &Bp[wn * 32 + ni * 8 + (l & 7)][ks * 16 + ((l >> 3) & 1) * 8]));
#pragma unroll
                for (int mi = 0; mi < 4; mi++)
#pragma unroll
                    for (int ni = 0; ni < 4; ni++)
                        mma16816(acc[mi][ni], af[mi], bf[ni]);
            }
        }
        __syncthreads();
    }

    // ---- epilogue: add bias, store ----
#pragma unroll
    for (int ni = 0; ni < 4; ni++) {
        const int gn = n0 + wn * 32 + ni * 8 + (l & 3) * 2;
        const float b0 = g_bias[gn], b1 = g_bias[gn + 1];
#pragma unroll
        for (int mi = 0; mi < 4; mi++) {
            const int gm = m0 + wm * 64 + mi * 16 + (l >> 2);
            float2 v0 = {acc[mi][ni][0] + b0, acc[mi][ni][1] + b1};
            float2 v1 = {acc[mi][ni][2] + b0, acc[mi][ni][3] + b1};
            *(float2*)&g_preact[(size_t)gm * G4H + gn]       = v0;
            *(float2*)&g_preact[(size_t)(gm + 8) * G4H + gn] = v1;
        }
    }
}

// ---------------------------------------------------------------------------
// Kernel 2: persistent recurrent kernel.
// 128 blocks = 16 j-slices x 8 batch-slices; group barrier per batch-slice
// (16 blocks). FFMA2 packed f32x2 inner loop (even/odd k lanes).
// ---------------------------------------------------------------------------
__global__ void __launch_bounds__(256, 1) lstm_rec_kernel(
    const float* __restrict__ h0, const float* __restrict__ c0,
    const float* __restrict__ Wh, float* __restrict__ out)
{
    __shared__ float hs[8][256];        // h tile: 8 batches x 256
    __shared__ float reds[64 * 33];     // K-partial reduction

    const int u   = threadIdx.x;
    const int jb  = blockIdx.x & 15;
    const int bb  = blockIdx.x >> 4;
    const int j0  = jb * 16;
    const int b0  = bb * 8;

    const int wid = u >> 5;
    const int l   = u & 31;
    const int ch  = wid >> 2;
    const int kq  = wid & 3;            // k quarter (64 k each)
    const int cmb = ch * 32 + l;        // 0..63 : (gate, local j)
    const int g   = cmb >> 4;
    const int jj  = cmb & 15;

    // pack this thread's 64 weights as 32 f32x2 pairs
    ull wp[32];
    {
        const float* wrow = Wh + (size_t)(g * HID + j0 + jj) * HID + kq * 64;
#pragma unroll
        for (int q = 0; q < 16; q++) {
            float4 v = *(const float4*)&wrow[q * 4];
            wp[q * 2 + 0] = pk2(v.x, v.y);
            wp[q * 2 + 1] = pk2(v.z, v.w);
        }
    }

    const int tb = u >> 4;   // 0..7  (valid for u<128)
    const int tj = u & 15;
    float cst = 0.f, hlast = 0.f;
    if (u < 128) cst = c0[(b0 + tb) * HID + j0 + tj];

    unsigned int* const cnt = &g_barG[bb * 32];

    // preload preact for t = 0
    float px0 = 0.f, px1 = 0.f, px2 = 0.f, px3 = 0.f;
    if (u < 128) {
        const float* pp = g_preact + ((size_t)0 * BATCH + b0 + tb) * G4H + j0 + tj;
        px0 = pp[0 * HID]; px1 = pp[1 * HID]; px2 = pp[2 * HID]; px3 = pp[3 * HID];
    }

    for (int t = 0; t < SEQ; t++) {
        // load h_t tile into smem (L2 only; never stale L1)
        {
            const float* hsrc = (t == 0) ? h0 : g_hbuf[t & 1];
#pragma unroll
            for (int q = 0; q < 2; q++) {
                int f  = u * 2 + q;
                int b  = f >> 6;
                int ko = (f & 63) * 4;
                float4 v = __ldcg((const float4*)&hsrc[(size_t)(b0 + b) * HID + ko]);
                *(float4*)&hs[b][ko] = v;
            }
        }
        __syncthreads();

        // prefetch preact for t+1 (off critical path, hides DRAM latency)
        float nx0 = 0.f, nx1 = 0.f, nx2 = 0.f, nx3 = 0.f;
        if (u < 128) {
            int tn = (t + 1 < SEQ) ? (t + 1) : t;
            const float* pp = g_preact + ((size_t)tn * BATCH + b0 + tb) * G4H + j0 + tj;
            nx0 = pp[0 * HID]; nx1 = pp[1 * HID]; nx2 = pp[2 * HID]; nx3 = pp[3 * HID];
        }

        // packed-f32x2 GEMM over this thread's k-quarter
        ull acc2[8];
#pragma unroll
        for (int b = 0; b < 8; b++) acc2[b] = 0ull;
#pragma unroll
        for (int k4 = 0; k4 < 16; k4++) {
            const ull w0 = wp[k4 * 2 + 0], w1 = wp[k4 * 2 + 1];
#pragma unroll
            for (int b = 0; b < 8; b++) {
                ulonglong2 hv = *(const ulonglong2*)&hs[b][kq * 64 + k4 * 4];
                acc2[b] = ffma2(hv.x, w0, acc2[b]);
                acc2[b] = ffma2(hv.y, w1, acc2[b]);
            }
        }
#pragma unroll
        for (int b = 0; b < 8; b++) {
            float lo, hi; upk2(acc2[b], lo, hi);
            reds[cmb * 33 + kq * 8 + b] = lo + hi;
        }
        __syncthreads();

        if (u < 128) {
            float p[4];
#pragma unroll
            for (int gg = 0; gg < 4; gg++) {
                int cc = gg * 16 + tj;
                p[gg] = reds[cc * 33 + 0 + tb] + reds[cc * 33 + 8 + tb]
                      + reds[cc * 33 + 16 + tb] + reds[cc * 33 + 24 + tb];
            }
            p[0] += px0; p[1] += px1; p[2] += px2; p[3] += px3;

            float it = sigf(p[0]);
            float ft = sigf(p[1]);
            float ot = sigf(p[2]);
            float gt = tanhf_(p[3]);
            cst = cst * ft + it * gt;
            float ht = ot * tanhf_(cst);
            hlast = ht;

            out[((size_t)t * BATCH + b0 + tb) * HID + j0 + tj] = ht;
            g_hbuf[(t + 1) & 1][(b0 + tb) * HID + j0 + tj] = ht;
        }
        __syncthreads();

        if (t < SEQ - 1) {
            if (u == 0) {
                __threadfence();            // release h writes
                atomicAdd(cnt, 1u);
                const unsigned target = (unsigned)(t + 1) * 16u;
                unsigned v;
                do {
                    asm volatile("ld.acquire.gpu.global.u32 %0, [%1];"
                                 : "=r"(v) : "l"(cnt) : "memory");
                } while (v < target);
            }
            __syncthreads();
        }
        px0 = nx0; px1 = nx1; px2 = nx2; px3 = nx3;
    }

    if (u < 128) {
        const size_t base = (size_t)SEQ * BATCH * HID;
        const int idx = (b0 + tb) * HID + j0 + tj;
        out[base + idx]               = hlast;
        out[base + BATCH * HID + idx] = cst;
    }
}

// ---------------------------------------------------------------------------
extern "C" void kernel_launch(void* const* d_in, const int* in_sizes, int n_in,
                              void* d_out, int out_size)
{
    const float* x  = (const float*)d_in[0];
    const float* h0 = (const float*)d_in[1];
    const float* c0 = (const float*)d_in[2];
    const float* Wi = (const float*)d_in[3];
    const float* bi = (const float*)d_in[4];
    const float* Wh = (const float*)d_in[5];
    const float* bh = (const float*)d_in[6];
    float* out = (float*)d_out;

    convert_x_kernel<<<8192, 256>>>(x);
    convert_w_kernel<<<256, 256>>>(Wi, bi, bh);

    dim3 gg(G4H / 128, MTOT / 128);   // (8, 1024)
    gemm_mma_kernel<<<gg, 256>>>();

    lstm_rec_kernel<<<128, 256>>>(h0, c0, Wh, out);
}